// round 16
// baseline (speedup 1.0000x reference)
#include <cuda_runtime.h>
#include <cuda_bf16.h>
#include <cuda_fp16.h>
#include <cstdint>

#define DN   128
#define DE   64
#define NMAX 50000

__device__ float g_sums[(size_t)NMAX * DN];
__device__ float g_xp[(size_t)NMAX * DN];
__device__ float g_cnt[NMAX];
__device__ int   g_is64;

__device__ __forceinline__ float lrelu(float v) { return v > 0.f ? v : 0.01f * v; }

__device__ __forceinline__ uint32_t smem_u32(const void* p) {
    uint32_t a;
    asm("{ .reg .u64 t; cvta.to.shared.u64 t, %1; cvt.u32.u64 %0, t; }" : "=r"(a) : "l"(p));
    return a;
}

__device__ __forceinline__ void ldsm4(uint32_t addr, uint32_t r[4]) {
    asm volatile("ldmatrix.sync.aligned.m8n8.x4.shared.b16 {%0,%1,%2,%3}, [%4];"
                 : "=r"(r[0]), "=r"(r[1]), "=r"(r[2]), "=r"(r[3]) : "r"(addr));
}

__device__ __forceinline__ void mma16816h(float c[4], const uint32_t a[4], const uint32_t b[2]) {
    asm volatile("mma.sync.aligned.m16n8k16.row.col.f32.f16.f16.f32 "
                 "{%0,%1,%2,%3}, {%4,%5,%6,%7}, {%8,%9}, {%0,%1,%2,%3};"
                 : "+f"(c[0]), "+f"(c[1]), "+f"(c[2]), "+f"(c[3])
                 : "r"(a[0]), "r"(a[1]), "r"(a[2]), "r"(a[3]), "r"(b[0]), "r"(b[1]));
}

__device__ __forceinline__ void pack4h(float4 v, uint32_t& h01, uint32_t& h23) {
    __half2 a = __floats2half2_rn(v.x, v.y);
    __half2 b = __floats2half2_rn(v.z, v.w);
    h01 = *(uint32_t*)&a; h23 = *(uint32_t*)&b;
}
__device__ __forceinline__ void split4h(float4 v, uint32_t& h01, uint32_t& h23,
                                        uint32_t& l01, uint32_t& l23) {
    __half2 a = __floats2half2_rn(v.x, v.y);
    __half2 b = __floats2half2_rn(v.z, v.w);
    __half2 c = __floats2half2_rn(v.x - __half2float(__low2half(a)),
                                  v.y - __half2float(__high2half(a)));
    __half2 d = __floats2half2_rn(v.z - __half2float(__low2half(b)),
                                  v.w - __half2float(__high2half(b)));
    h01 = *(uint32_t*)&a; h23 = *(uint32_t*)&b;
    l01 = *(uint32_t*)&c; l23 = *(uint32_t*)&d;
}

// 2-term fp16 split GEMM (node/xprime)
template <int KB, int KS>
__device__ __forceinline__ void mma_core2h(uint32_t aH, uint32_t aL, uint32_t bH,
                                           int m0, int n0, int lane, float c[4][4])
{
#pragma unroll
    for (int nt = 0; nt < 4; ++nt)
#pragma unroll
        for (int j = 0; j < 4; ++j) c[nt][j] = 0.f;

    uint32_t rA = lane & 15;
    uint32_t kA = (lane >> 4) << 4;
    uint32_t xA = (rA & 7) << 4;
    uint32_t rB = ((lane >> 4) & 1) * 8 + (lane & 7);
    uint32_t kB = ((lane >> 3) & 1) << 4;
    uint32_t xB = (rB & 7) << 4;
    uint32_t aRH = aH + (m0 + rA) * KB;
    uint32_t aRL = aL + (m0 + rA) * KB;
    uint32_t bRH = bH + (n0 + rB) * KB;

#pragma unroll
    for (int ks = 0; ks < KS; ++ks) {
        uint32_t colA = (((uint32_t)ks * 32) | kA) ^ xA;
        uint32_t colB = (((uint32_t)ks * 32) | kB) ^ xB;
        uint32_t ah[4], al[4], bh[2][4];
        ldsm4(aRH + colA, ah);
        ldsm4(aRL + colA, al);
#pragma unroll
        for (int p = 0; p < 2; ++p) ldsm4(bRH + p * 16 * KB + colB, bh[p]);
#pragma unroll
        for (int nt = 0; nt < 4; ++nt) {
            const uint32_t* bbh = &bh[nt >> 1][(nt & 1) * 2];
            mma16816h(c[nt], ah, bbh);
            mma16816h(c[nt], al, bbh);
        }
    }
}

// ---------------- small kernels -------------------------------------------------
__global__ void detect_kernel(const unsigned* __restrict__ w, int E)
{
    __shared__ unsigned accsh;
    if (threadIdx.x == 0) accsh = 0u;
    __syncthreads();
    int nscan = 4096; if (nscan > E) nscan = E;
    unsigned nz = 0;
    for (int i = threadIdx.x; i < nscan; i += blockDim.x) nz |= w[2 * i + 1];
#pragma unroll
    for (int o = 16; o > 0; o >>= 1) nz |= __shfl_xor_sync(0xffffffffu, nz, o);
    if ((threadIdx.x & 31) == 0) atomicOr(&accsh, nz);
    __syncthreads();
    if (threadIdx.x == 0) g_is64 = (accsh == 0u) ? 1 : 0;
}

__global__ void zero_kernel(int N)
{
    int tid = blockIdx.x * blockDim.x + threadIdx.x;
    int stride = gridDim.x * blockDim.x;
    float4 z = make_float4(0.f, 0.f, 0.f, 0.f);
    float4* s4 = (float4*)g_sums;
    int n4 = N * (DN / 4);
    for (int i = tid; i < n4; i += stride) s4[i] = z;
    for (int i = tid; i < N; i += stride) g_cnt[i] = 0.f;
}

#define CSTRIDE 132

// ---------------- xprime kernel (unchanged from R15) ----------------------------
#define X_BH 0
#define X_A  32768
#define X_AL 57344
#define X_C  81920
#define SMEM_XP 132608

__global__ void __launch_bounds__(768, 1) xprime_kernel(
    const float* __restrict__ x, const float* __restrict__ W1, int N)
{
    extern __shared__ char smem[];
    const uint32_t sb = smem_u32(smem);
    float* sC = (float*)(smem + X_C);

    int tid = threadIdx.x, wid = tid >> 5, lane = tid & 31;
    int m0 = (wid >> 2) * 16, n0 = (wid & 3) * 32;

    for (int i = tid; i < 128 * 128; i += 768) {
        int n = i >> 7, k = i & 127;
        __half hb = __float2half_rn(W1[(size_t)k * DN + n]);
        unsigned short h = *(unsigned short*)&hb;
        uint32_t a = sb + X_BH + n * 256 + (((uint32_t)(2 * k)) ^ (((uint32_t)(n & 7)) << 4));
        asm volatile("st.shared.b16 [%0], %1;" :: "r"(a), "h"(h));
    }

    int ntiles = (N + 95) / 96;
    float4 v[4];

    int t = blockIdx.x;
    if (t < ntiles) {
        int nb = t * 96;
#pragma unroll
        for (int j = 0; j < 4; ++j) {
            int i = tid + j * 768;
            int r = i >> 5, q = i & 31;
            int n = nb + r;
            v[j] = (n < N) ? *(const float4*)&x[(size_t)n * DN + q * 4]
                           : make_float4(0.f, 0.f, 0.f, 0.f);
        }
#pragma unroll
        for (int j = 0; j < 4; ++j) {
            int i = tid + j * 768;
            int r = i >> 5, q = i & 31;
            uint32_t h01, h23, l01, l23;
            split4h(v[j], h01, h23, l01, l23);
            uint32_t a = sb + X_A + r * 256 + (((uint32_t)(8 * q)) ^ (((uint32_t)(r & 7)) << 4));
            asm volatile("st.shared.v2.b32 [%0], {%1,%2};" :: "r"(a), "r"(h01), "r"(h23));
            asm volatile("st.shared.v2.b32 [%0], {%1,%2};" :: "r"(a + (X_AL - X_A)), "r"(l01), "r"(l23));
        }
    }
    __syncthreads();

    for (; t < ntiles; t += gridDim.x) {
        int tn = t + gridDim.x;
        if (tn < ntiles) {
            int nb = tn * 96;
#pragma unroll
            for (int j = 0; j < 4; ++j) {
                int i = tid + j * 768;
                int r = i >> 5, q = i & 31;
                int n = nb + r;
                v[j] = (n < N) ? *(const float4*)&x[(size_t)n * DN + q * 4]
                               : make_float4(0.f, 0.f, 0.f, 0.f);
            }
        }

        float c[4][4];
        mma_core2h<256, 8>(sb + X_A, sb + X_AL, sb + X_BH, m0, n0, lane, c);

        int rlo = lane >> 2, cp = (lane & 3) * 2;
#pragma unroll
        for (int nt = 0; nt < 4; ++nt) {
            int row = m0 + rlo, col = n0 + nt * 8 + cp;
            *(float2*)&sC[row * CSTRIDE + col]       = make_float2(c[nt][0], c[nt][1]);
            *(float2*)&sC[(row + 8) * CSTRIDE + col] = make_float2(c[nt][2], c[nt][3]);
        }
        __syncthreads();

        {
            int nb = t * 96;
            int c0 = lane * 4;
#pragma unroll
            for (int j = 0; j < 4; ++j) {
                int r = wid * 4 + j;
                int n = nb + r;
                if (n < N) {
                    float4 cv = *(const float4*)&sC[r * CSTRIDE + c0];
                    *(float4*)&g_xp[(size_t)n * DN + c0] = cv;
                }
            }
        }

        if (tn < ntiles) {
#pragma unroll
            for (int j = 0; j < 4; ++j) {
                int i = tid + j * 768;
                int r = i >> 5, q = i & 31;
                uint32_t h01, h23, l01, l23;
                split4h(v[j], h01, h23, l01, l23);
                uint32_t a = sb + X_A + r * 256 + (((uint32_t)(8 * q)) ^ (((uint32_t)(r & 7)) << 4));
                asm volatile("st.shared.v2.b32 [%0], {%1,%2};" :: "r"(a), "r"(h01), "r"(h23));
                asm volatile("st.shared.v2.b32 [%0], {%1,%2};" :: "r"(a + (X_AL - X_A)), "r"(l01), "r"(l23));
            }
        }
        __syncthreads();
    }
}

// ---------------- edge kernel: B register-resident, fp16 C, split gather --------
#define E_BH 0              // B staging: 128 * 128B = 16384 (read once)
#define E_A  16384          // A: 64*128 = 8192
#define E_C  24576          // fp16 C: 64*132*2 = 16896
#define E_P  41472
#define SMEM_EDGE 43008

__global__ void __launch_bounds__(512, 2) edge_kernel(
    const void* __restrict__ eidx, const float* __restrict__ ea,
    const float* __restrict__ W1, const float* __restrict__ b1,
    const float* __restrict__ g1, const float* __restrict__ be1, int N, int E)
{
    extern __shared__ char smem[];
    const uint32_t sb = smem_u32(smem);
    __half* sCh = (__half*)(smem + E_C);
    float* sP = (float*)(smem + E_P);

    int tid = threadIdx.x, wid = tid >> 5, lane = tid & 31;
    int m0 = (wid >> 2) * 16, n0 = (wid & 3) * 32;

    // stage B = W1b^T fp16 into smem (once)
    for (int i = tid; i < 128 * 64; i += 512) {
        int n = i >> 6, k = i & 63;
        __half hb = __float2half_rn(W1[(size_t)(128 + k) * DN + n]);
        unsigned short h = *(unsigned short*)&hb;
        uint32_t a = sb + E_BH + n * 128 + (((uint32_t)(2 * k)) ^ (((uint32_t)(n & 7)) << 4));
        asm volatile("st.shared.b16 [%0], %1;" :: "r"(a), "h"(h));
    }
    for (int i = tid; i < DN; i += 512) { sP[i] = b1[i]; sP[DN + i] = g1[i]; sP[2 * DN + i] = be1[i]; }
    __syncthreads();

    // preload ALL B fragments into registers (4 k-steps x 2 ldsm.x4 = 32 regs)
    uint32_t breg[4][2][4];
    {
        uint32_t rB = ((lane >> 4) & 1) * 8 + (lane & 7);
        uint32_t kB = ((lane >> 3) & 1) << 4;
        uint32_t xB = (rB & 7) << 4;
        uint32_t bR = sb + E_BH + (n0 + rB) * 128;
#pragma unroll
        for (int ks = 0; ks < 4; ++ks) {
            uint32_t colB = (((uint32_t)ks * 32) | kB) ^ xB;
#pragma unroll
            for (int p = 0; p < 2; ++p)
                ldsm4(bR + p * 16 * 128 + colB, breg[ks][p]);
        }
    }

    const int is64 = g_is64;
    const long long* ei64 = (const long long*)eidx;
    const int*       ei32 = (const int*)eidx;

    int ntiles = (E + 63) >> 6;
    float4 va, vb;

    // gather half h (thread covers 1 float4 per half) of tile tt
    auto GATHER = [&](int tt, int h, float4& dst) {
        int i = tid + h * 512;
        int r = i >> 4, q = i & 15;
        int e = (tt << 6) + r;
        dst = (e < E) ? *(const float4*)&ea[(size_t)e * DE + q * 4]
                      : make_float4(0.f, 0.f, 0.f, 0.f);
    };
    auto CONVERT = [&](int h, float4 src) {
        int i = tid + h * 512;
        int r = i >> 4, q = i & 15;
        uint32_t h01, h23;
        pack4h(src, h01, h23);
        uint32_t a = sb + E_A + r * 128 + (((uint32_t)(8 * q)) ^ (((uint32_t)(r & 7)) << 4));
        asm volatile("st.shared.v2.b32 [%0], {%1,%2};" :: "r"(a), "r"(h01), "r"(h23));
    };

    int t = blockIdx.x;
    if (t < ntiles) {
        GATHER(t, 0, va); CONVERT(0, va);
        GATHER(t, 1, va); CONVERT(1, va);
    }
    __syncthreads();

    for (; t < ntiles; t += gridDim.x) {
        int tn = t + gridDim.x;
        if (tn < ntiles) GATHER(tn, 0, va);    // half 1: lives across mma (4 regs)

        // mma: A from smem, B from registers
        float c[4][4];
        {
#pragma unroll
            for (int nt = 0; nt < 4; ++nt)
#pragma unroll
                for (int j = 0; j < 4; ++j) c[nt][j] = 0.f;
            uint32_t rA = lane & 15;
            uint32_t kA = (lane >> 4) << 4;
            uint32_t xA = (rA & 7) << 4;
            uint32_t aR = sb + E_A + (m0 + rA) * 128;
#pragma unroll
            for (int ks = 0; ks < 4; ++ks) {
                uint32_t colA = (((uint32_t)ks * 32) | kA) ^ xA;
                uint32_t ah[4];
                ldsm4(aR + colA, ah);
#pragma unroll
                for (int nt = 0; nt < 4; ++nt)
                    mma16816h(c[nt], ah, &breg[ks][nt >> 1][(nt & 1) * 2]);
            }
        }

        // store C fp16
        int rlo = lane >> 2, cp = (lane & 3) * 2;
#pragma unroll
        for (int nt = 0; nt < 4; ++nt) {
            int row = m0 + rlo, col = n0 + nt * 8 + cp;
            *(__half2*)&sCh[row * CSTRIDE + col]       = __floats2half2_rn(c[nt][0], c[nt][1]);
            *(__half2*)&sCh[(row + 8) * CSTRIDE + col] = __floats2half2_rn(c[nt][2], c[nt][3]);
        }
        __syncthreads();   // C visible; all mma A-reads done

        if (tn < ntiles) GATHER(tn, 1, vb);    // half 2: hides under epilogue

        // epilogue: warp owns rows [4*wid, 4*wid+4)
        {
            int e0 = t << 6;
            int c0 = lane * 4;
            float4 bb  = *(const float4*)&sP[c0];
            float4 gg  = *(const float4*)&sP[DN + c0];
            float4 beb = *(const float4*)&sP[2 * DN + c0];
#pragma unroll
            for (int j = 0; j < 4; ++j) {
                int r = wid * 4 + j;
                int e = e0 + r;
                int src = 0, dst = 0;
                if (e < E) {
                    src = is64 ? (int)ei64[e] : ei32[e];
                    dst = is64 ? (int)ei64[(size_t)E + e] : ei32[E + e];
                }
                float4 xp = (e < E) ? *(const float4*)&g_xp[(size_t)src * DN + c0]
                                    : make_float4(0.f, 0.f, 0.f, 0.f);
                uint2 u = *(const uint2*)&sCh[r * CSTRIDE + c0];
                __half2 ch0 = *(__half2*)&u.x, ch1 = *(__half2*)&u.y;
                float v0 = __low2float(ch0)  + xp.x + bb.x;
                float v1 = __high2float(ch0) + xp.y + bb.y;
                float v2 = __low2float(ch1)  + xp.z + bb.z;
                float v3 = __high2float(ch1) + xp.w + bb.w;
                float s = v0 + v1 + v2 + v3;
                float q = fmaf(v0, v0, fmaf(v1, v1, fmaf(v2, v2, v3 * v3)));
#pragma unroll
                for (int o = 16; o > 0; o >>= 1) {
                    s += __shfl_xor_sync(0xffffffffu, s, o);
                    q += __shfl_xor_sync(0xffffffffu, q, o);
                }
                const float inv = 0.0078125f;
                float mean = s * inv;
                float var  = fmaf(q, inv, -mean * mean);
                float rstd = rsqrtf(var + 1e-5f);
                float o0 = lrelu(fmaf((v0 - mean) * rstd, gg.x, beb.x));
                float o1 = lrelu(fmaf((v1 - mean) * rstd, gg.y, beb.y));
                float o2 = lrelu(fmaf((v2 - mean) * rstd, gg.z, beb.z));
                float o3 = lrelu(fmaf((v3 - mean) * rstd, gg.w, beb.w));
                if (e < E) {
                    float* p = g_sums + (size_t)dst * DN + c0;
                    asm volatile("red.global.add.v4.f32 [%0], {%1,%2,%3,%4};"
                                 :: "l"(p), "f"(o0), "f"(o1), "f"(o2), "f"(o3) : "memory");
                    if (lane == 0) atomicAdd(g_cnt + dst, 1.0f);
                }
            }
        }

        if (tn < ntiles) { CONVERT(0, va); CONVERT(1, vb); }
        __syncthreads();   // A(tn) ready; C reads done
    }
}

// ---------------- node kernel (unchanged from R15) ------------------------------
#define N_BH 0
#define N_A  32768
#define N_AL 57344
#define N_C  81920
#define N_P  132608
#define SMEM_NODE 134144

__global__ void __launch_bounds__(768, 1) node_kernel(
    const float* __restrict__ x, const float* __restrict__ W2,
    const float* __restrict__ b2, const float* __restrict__ g2,
    const float* __restrict__ be2, float* __restrict__ out, int N)
{
    extern __shared__ char smem[];
    const uint32_t sb = smem_u32(smem);
    float* sC = (float*)(smem + N_C);
    float* sP = (float*)(smem + N_P);

    int tid = threadIdx.x, wid = tid >> 5, lane = tid & 31;
    int m0 = (wid >> 2) * 16, n0 = (wid & 3) * 32;

    for (int i = tid; i < 128 * 128; i += 768) {
        int n = i >> 7, k = i & 127;
        __half hb = __float2half_rn(W2[(size_t)k * DN + n]);
        unsigned short h = *(unsigned short*)&hb;
        uint32_t a = sb + N_BH + n * 256 + (((uint32_t)(2 * k)) ^ (((uint32_t)(n & 7)) << 4));
        asm volatile("st.shared.b16 [%0], %1;" :: "r"(a), "h"(h));
    }
    for (int i = tid; i < DN; i += 768) { sP[i] = b2[i]; sP[DN + i] = g2[i]; sP[2 * DN + i] = be2[i]; }

    int ntiles = (N + 95) / 96;
    float4 v[4];

    int t = blockIdx.x;
    if (t < ntiles) {
        int nb = t * 96;
#pragma unroll
        for (int j = 0; j < 4; ++j) {
            int i = tid + j * 768;
            int r = i >> 5, q = i & 31;
            int n = nb + r;
            float4 val = make_float4(0.f, 0.f, 0.f, 0.f);
            if (n < N) {
                float sc = 1.0f / fmaxf(g_cnt[n], 1.0f);
                val = *(const float4*)&g_sums[(size_t)n * DN + q * 4];
                val.x *= sc; val.y *= sc; val.z *= sc; val.w *= sc;
            }
            v[j] = val;
        }
#pragma unroll
        for (int j = 0; j < 4; ++j) {
            int i = tid + j * 768;
            int r = i >> 5, q = i & 31;
            uint32_t h01, h23, l01, l23;
            split4h(v[j], h01, h23, l01, l23);
            uint32_t a = sb + N_A + r * 256 + (((uint32_t)(8 * q)) ^ (((uint32_t)(r & 7)) << 4));
            asm volatile("st.shared.v2.b32 [%0], {%1,%2};" :: "r"(a), "r"(h01), "r"(h23));
            asm volatile("st.shared.v2.b32 [%0], {%1,%2};" :: "r"(a + (N_AL - N_A)), "r"(l01), "r"(l23));
        }
    }
    __syncthreads();

    for (; t < ntiles; t += gridDim.x) {
        int tn = t + gridDim.x;
        if (tn < ntiles) {
            int nb = tn * 96;
#pragma unroll
            for (int j = 0; j < 4; ++j) {
                int i = tid + j * 768;
                int r = i >> 5, q = i & 31;
                int n = nb + r;
                float4 val = make_float4(0.f, 0.f, 0.f, 0.f);
                if (n < N) {
                    float sc = 1.0f / fmaxf(g_cnt[n], 1.0f);
                    val = *(const float4*)&g_sums[(size_t)n * DN + q * 4];
                    val.x *= sc; val.y *= sc; val.z *= sc; val.w *= sc;
                }
                v[j] = val;
            }
        }

        float c[4][4];
        mma_core2h<256, 8>(sb + N_A, sb + N_AL, sb + N_BH, m0, n0, lane, c);

        int rlo = lane >> 2, cp = (lane & 3) * 2;
#pragma unroll
        for (int nt = 0; nt < 4; ++nt) {
            int row = m0 + rlo, col = n0 + nt * 8 + cp;
            *(float2*)&sC[row * CSTRIDE + col]       = make_float2(c[nt][0], c[nt][1]);
            *(float2*)&sC[(row + 8) * CSTRIDE + col] = make_float2(c[nt][2], c[nt][3]);
        }
        __syncthreads();

        {
            int nb = t * 96;
            int c0 = lane * 4;
            float4 bb  = *(const float4*)&sP[c0];
            float4 gg  = *(const float4*)&sP[DN + c0];
            float4 beb = *(const float4*)&sP[2 * DN + c0];
#pragma unroll
            for (int j = 0; j < 4; ++j) {
                int r = wid * 4 + j;
                int n = nb + r;
                float4 cv = *(const float4*)&sC[r * CSTRIDE + c0];
                float v0 = cv.x + bb.x, v1 = cv.y + bb.y, v2 = cv.z + bb.z, v3 = cv.w + bb.w;
                float s = v0 + v1 + v2 + v3;
                float q = fmaf(v0, v0, fmaf(v1, v1, fmaf(v2, v2, v3 * v3)));
#pragma unroll
                for (int o = 16; o > 0; o >>= 1) {
                    s += __shfl_xor_sync(0xffffffffu, s, o);
                    q += __shfl_xor_sync(0xffffffffu, q, o);
                }
                const float inv = 0.0078125f;
                float mean = s * inv;
                float var  = fmaf(q, inv, -mean * mean);
                float rstd = rsqrtf(var + 1e-5f);
                float o0 = lrelu(fmaf((v0 - mean) * rstd, gg.x, beb.x));
                float o1 = lrelu(fmaf((v1 - mean) * rstd, gg.y, beb.y));
                float o2 = lrelu(fmaf((v2 - mean) * rstd, gg.z, beb.z));
                float o3 = lrelu(fmaf((v3 - mean) * rstd, gg.w, beb.w));
                if (n < N) {
                    float4 xr = *(const float4*)&x[(size_t)n * DN + c0];
                    o0 = lrelu(o0 + xr.x);
                    o1 = lrelu(o1 + xr.y);
                    o2 = lrelu(o2 + xr.z);
                    o3 = lrelu(o3 + xr.w);
                    *(float4*)&out[(size_t)n * DN + c0] = make_float4(o0, o1, o2, o3);
                }
            }
        }

        if (tn < ntiles) {
#pragma unroll
            for (int j = 0; j < 4; ++j) {
                int i = tid + j * 768;
                int r = i >> 5, q = i & 31;
                uint32_t h01, h23, l01, l23;
                split4h(v[j], h01, h23, l01, l23);
                uint32_t a = sb + N_A + r * 256 + (((uint32_t)(8 * q)) ^ (((uint32_t)(r & 7)) << 4));
                asm volatile("st.shared.v2.b32 [%0], {%1,%2};" :: "r"(a), "r"(h01), "r"(h23));
                asm volatile("st.shared.v2.b32 [%0], {%1,%2};" :: "r"(a + (N_AL - N_A)), "r"(l01), "r"(l23));
            }
        }
        __syncthreads();
    }
}

// ---------------- launch ----------------------------------------------------------
extern "C" void kernel_launch(void* const* d_in, const int* in_sizes, int n_in,
                              void* d_out, int out_size)
{
    const float* x   = (const float*)d_in[0];
    const void*  ei  = d_in[1];
    const float* ea  = (const float*)d_in[2];
    const float* W1  = (const float*)d_in[3];
    const float* b1  = (const float*)d_in[4];
    const float* g1  = (const float*)d_in[5];
    const float* be1 = (const float*)d_in[6];
    const float* W2  = (const float*)d_in[7];
    const float* b2  = (const float*)d_in[8];
    const float* g2  = (const float*)d_in[9];
    const float* be2 = (const float*)d_in[10];
    float* out = (float*)d_out;

    int N = in_sizes[0] / DN;
    int E = in_sizes[2] / DE;

    cudaFuncSetAttribute(xprime_kernel, cudaFuncAttributeMaxDynamicSharedMemorySize, SMEM_XP);
    cudaFuncSetAttribute(edge_kernel,   cudaFuncAttributeMaxDynamicSharedMemorySize, SMEM_EDGE);
    cudaFuncSetAttribute(node_kernel,   cudaFuncAttributeMaxDynamicSharedMemorySize, SMEM_NODE);

    detect_kernel<<<1, 256>>>((const unsigned*)ei, E);
    zero_kernel<<<512, 256>>>(N);
    xprime_kernel<<<148, 768, SMEM_XP>>>(x, W1, N);
    edge_kernel<<<296, 512, SMEM_EDGE>>>(ei, ea, W1, b1, g1, be1, N, E);
    node_kernel<<<148, 768, SMEM_NODE>>>(x, W2, b2, g2, be2, out, N);
}

// round 17
// speedup vs baseline: 1.1237x; 1.1237x over previous
#include <cuda_runtime.h>
#include <cuda_bf16.h>
#include <cuda_fp16.h>
#include <cstdint>

#define DN   128
#define DE   64
#define NMAX 50000

__device__ float g_sums[(size_t)NMAX * DN];
__device__ float g_xp[(size_t)NMAX * DN];
__device__ float g_cnt[NMAX];
__device__ int   g_is64;

__device__ __forceinline__ float lrelu(float v) { return v > 0.f ? v : 0.01f * v; }

__device__ __forceinline__ uint32_t smem_u32(const void* p) {
    uint32_t a;
    asm("{ .reg .u64 t; cvta.to.shared.u64 t, %1; cvt.u32.u64 %0, t; }" : "=r"(a) : "l"(p));
    return a;
}

__device__ __forceinline__ void ldsm4(uint32_t addr, uint32_t r[4]) {
    asm volatile("ldmatrix.sync.aligned.m8n8.x4.shared.b16 {%0,%1,%2,%3}, [%4];"
                 : "=r"(r[0]), "=r"(r[1]), "=r"(r[2]), "=r"(r[3]) : "r"(addr));
}

__device__ __forceinline__ void mma16816h(float c[4], const uint32_t a[4], const uint32_t b[2]) {
    asm volatile("mma.sync.aligned.m16n8k16.row.col.f32.f16.f16.f32 "
                 "{%0,%1,%2,%3}, {%4,%5,%6,%7}, {%8,%9}, {%0,%1,%2,%3};"
                 : "+f"(c[0]), "+f"(c[1]), "+f"(c[2]), "+f"(c[3])
                 : "r"(a[0]), "r"(a[1]), "r"(a[2]), "r"(a[3]), "r"(b[0]), "r"(b[1]));
}

__device__ __forceinline__ void pack4h(float4 v, uint32_t& h01, uint32_t& h23) {
    __half2 a = __floats2half2_rn(v.x, v.y);
    __half2 b = __floats2half2_rn(v.z, v.w);
    h01 = *(uint32_t*)&a; h23 = *(uint32_t*)&b;
}
__device__ __forceinline__ void split4h(float4 v, uint32_t& h01, uint32_t& h23,
                                        uint32_t& l01, uint32_t& l23) {
    __half2 a = __floats2half2_rn(v.x, v.y);
    __half2 b = __floats2half2_rn(v.z, v.w);
    __half2 c = __floats2half2_rn(v.x - __half2float(__low2half(a)),
                                  v.y - __half2float(__high2half(a)));
    __half2 d = __floats2half2_rn(v.z - __half2float(__low2half(b)),
                                  v.w - __half2float(__high2half(b)));
    h01 = *(uint32_t*)&a; h23 = *(uint32_t*)&b;
    l01 = *(uint32_t*)&c; l23 = *(uint32_t*)&d;
}

// 2-term fp16 split GEMM (node/xprime)
template <int KB, int KS>
__device__ __forceinline__ void mma_core2h(uint32_t aH, uint32_t aL, uint32_t bH,
                                           int m0, int n0, int lane, float c[4][4])
{
#pragma unroll
    for (int nt = 0; nt < 4; ++nt)
#pragma unroll
        for (int j = 0; j < 4; ++j) c[nt][j] = 0.f;

    uint32_t rA = lane & 15;
    uint32_t kA = (lane >> 4) << 4;
    uint32_t xA = (rA & 7) << 4;
    uint32_t rB = ((lane >> 4) & 1) * 8 + (lane & 7);
    uint32_t kB = ((lane >> 3) & 1) << 4;
    uint32_t xB = (rB & 7) << 4;
    uint32_t aRH = aH + (m0 + rA) * KB;
    uint32_t aRL = aL + (m0 + rA) * KB;
    uint32_t bRH = bH + (n0 + rB) * KB;

#pragma unroll
    for (int ks = 0; ks < KS; ++ks) {
        uint32_t colA = (((uint32_t)ks * 32) | kA) ^ xA;
        uint32_t colB = (((uint32_t)ks * 32) | kB) ^ xB;
        uint32_t ah[4], al[4], bh[2][4];
        ldsm4(aRH + colA, ah);
        ldsm4(aRL + colA, al);
#pragma unroll
        for (int p = 0; p < 2; ++p) ldsm4(bRH + p * 16 * KB + colB, bh[p]);
#pragma unroll
        for (int nt = 0; nt < 4; ++nt) {
            const uint32_t* bbh = &bh[nt >> 1][(nt & 1) * 2];
            mma16816h(c[nt], ah, bbh);
            mma16816h(c[nt], al, bbh);
        }
    }
}

// single-term fp16 GEMM: c += a*b
template <int KB, int KS>
__device__ __forceinline__ void mma_core1h(uint32_t aH, uint32_t bH,
                                           int m0, int n0, int lane, float c[4][4])
{
#pragma unroll
    for (int nt = 0; nt < 4; ++nt)
#pragma unroll
        for (int j = 0; j < 4; ++j) c[nt][j] = 0.f;

    uint32_t rA = lane & 15;
    uint32_t kA = (lane >> 4) << 4;
    uint32_t xA = (rA & 7) << 4;
    uint32_t rB = ((lane >> 4) & 1) * 8 + (lane & 7);
    uint32_t kB = ((lane >> 3) & 1) << 4;
    uint32_t xB = (rB & 7) << 4;
    uint32_t aRH = aH + (m0 + rA) * KB;
    uint32_t bRH = bH + (n0 + rB) * KB;

#pragma unroll
    for (int ks = 0; ks < KS; ++ks) {
        uint32_t colA = (((uint32_t)ks * 32) | kA) ^ xA;
        uint32_t colB = (((uint32_t)ks * 32) | kB) ^ xB;
        uint32_t ah[4], bh[2][4];
        ldsm4(aRH + colA, ah);
#pragma unroll
        for (int p = 0; p < 2; ++p) ldsm4(bRH + p * 16 * KB + colB, bh[p]);
#pragma unroll
        for (int nt = 0; nt < 4; ++nt) {
            const uint32_t* bbh = &bh[nt >> 1][(nt & 1) * 2];
            mma16816h(c[nt], ah, bbh);
        }
    }
}

// ---------------- small kernels -------------------------------------------------
__global__ void detect_kernel(const unsigned* __restrict__ w, int E)
{
    __shared__ unsigned accsh;
    if (threadIdx.x == 0) accsh = 0u;
    __syncthreads();
    int nscan = 4096; if (nscan > E) nscan = E;
    unsigned nz = 0;
    for (int i = threadIdx.x; i < nscan; i += blockDim.x) nz |= w[2 * i + 1];
#pragma unroll
    for (int o = 16; o > 0; o >>= 1) nz |= __shfl_xor_sync(0xffffffffu, nz, o);
    if ((threadIdx.x & 31) == 0) atomicOr(&accsh, nz);
    __syncthreads();
    if (threadIdx.x == 0) g_is64 = (accsh == 0u) ? 1 : 0;
}

__global__ void zero_kernel(int N)
{
    int tid = blockIdx.x * blockDim.x + threadIdx.x;
    int stride = gridDim.x * blockDim.x;
    float4 z = make_float4(0.f, 0.f, 0.f, 0.f);
    float4* s4 = (float4*)g_sums;
    int n4 = N * (DN / 4);
    for (int i = tid; i < n4; i += stride) s4[i] = z;
    for (int i = tid; i < N; i += stride) g_cnt[i] = 0.f;
}

#define CSTRIDE  132    // fp32 C stride (floats), node/xprime
#define ECSTRIDE 136    // fp16 C stride (halves) — 272B/row: conflict-free stores

// ---------------- xprime kernel: X' = x @ W1a (768 thr, fp16 2-term) ------------
#define X_BH 0
#define X_A  32768
#define X_AL 57344
#define X_C  81920
#define SMEM_XP 132608

__global__ void __launch_bounds__(768, 1) xprime_kernel(
    const float* __restrict__ x, const float* __restrict__ W1, int N)
{
    extern __shared__ char smem[];
    const uint32_t sb = smem_u32(smem);
    float* sC = (float*)(smem + X_C);

    int tid = threadIdx.x, wid = tid >> 5, lane = tid & 31;
    int m0 = (wid >> 2) * 16, n0 = (wid & 3) * 32;

    for (int i = tid; i < 128 * 128; i += 768) {
        int n = i >> 7, k = i & 127;
        __half hb = __float2half_rn(W1[(size_t)k * DN + n]);
        unsigned short h = *(unsigned short*)&hb;
        uint32_t a = sb + X_BH + n * 256 + (((uint32_t)(2 * k)) ^ (((uint32_t)(n & 7)) << 4));
        asm volatile("st.shared.b16 [%0], %1;" :: "r"(a), "h"(h));
    }

    int ntiles = (N + 95) / 96;
    float4 v[4];

    int t = blockIdx.x;
    if (t < ntiles) {
        int nb = t * 96;
#pragma unroll
        for (int j = 0; j < 4; ++j) {
            int i = tid + j * 768;
            int r = i >> 5, q = i & 31;
            int n = nb + r;
            v[j] = (n < N) ? *(const float4*)&x[(size_t)n * DN + q * 4]
                           : make_float4(0.f, 0.f, 0.f, 0.f);
        }
#pragma unroll
        for (int j = 0; j < 4; ++j) {
            int i = tid + j * 768;
            int r = i >> 5, q = i & 31;
            uint32_t h01, h23, l01, l23;
            split4h(v[j], h01, h23, l01, l23);
            uint32_t a = sb + X_A + r * 256 + (((uint32_t)(8 * q)) ^ (((uint32_t)(r & 7)) << 4));
            asm volatile("st.shared.v2.b32 [%0], {%1,%2};" :: "r"(a), "r"(h01), "r"(h23));
            asm volatile("st.shared.v2.b32 [%0], {%1,%2};" :: "r"(a + (X_AL - X_A)), "r"(l01), "r"(l23));
        }
    }
    __syncthreads();

    for (; t < ntiles; t += gridDim.x) {
        int tn = t + gridDim.x;
        if (tn < ntiles) {
            int nb = tn * 96;
#pragma unroll
            for (int j = 0; j < 4; ++j) {
                int i = tid + j * 768;
                int r = i >> 5, q = i & 31;
                int n = nb + r;
                v[j] = (n < N) ? *(const float4*)&x[(size_t)n * DN + q * 4]
                               : make_float4(0.f, 0.f, 0.f, 0.f);
            }
        }

        float c[4][4];
        mma_core2h<256, 8>(sb + X_A, sb + X_AL, sb + X_BH, m0, n0, lane, c);

        int rlo = lane >> 2, cp = (lane & 3) * 2;
#pragma unroll
        for (int nt = 0; nt < 4; ++nt) {
            int row = m0 + rlo, col = n0 + nt * 8 + cp;
            *(float2*)&sC[row * CSTRIDE + col]       = make_float2(c[nt][0], c[nt][1]);
            *(float2*)&sC[(row + 8) * CSTRIDE + col] = make_float2(c[nt][2], c[nt][3]);
        }
        __syncthreads();

        {
            int nb = t * 96;
            int c0 = lane * 4;
#pragma unroll
            for (int j = 0; j < 4; ++j) {
                int r = wid * 4 + j;
                int n = nb + r;
                if (n < N) {
                    float4 cv = *(const float4*)&sC[r * CSTRIDE + c0];
                    *(float4*)&g_xp[(size_t)n * DN + c0] = cv;
                }
            }
        }

        if (tn < ntiles) {
#pragma unroll
            for (int j = 0; j < 4; ++j) {
                int i = tid + j * 768;
                int r = i >> 5, q = i & 31;
                uint32_t h01, h23, l01, l23;
                split4h(v[j], h01, h23, l01, l23);
                uint32_t a = sb + X_A + r * 256 + (((uint32_t)(8 * q)) ^ (((uint32_t)(r & 7)) << 4));
                asm volatile("st.shared.v2.b32 [%0], {%1,%2};" :: "r"(a), "r"(h01), "r"(h23));
                asm volatile("st.shared.v2.b32 [%0], {%1,%2};" :: "r"(a + (X_AL - X_A)), "r"(l01), "r"(l23));
            }
        }
        __syncthreads();
    }
}

// ---------------- edge kernel: 512 thr x 2 CTA/SM, single fp16, fp16 C ----------
#define E_BH 0              // B: 128 * 128B = 16384
#define E_A  16384          // A: 64*128 = 8192
#define E_C  24576          // fp16 C: 64*136*2 = 17408
#define E_P  41984
#define SMEM_EDGE 43520

__global__ void __launch_bounds__(512, 2) edge_kernel(
    const void* __restrict__ eidx, const float* __restrict__ ea,
    const float* __restrict__ W1, const float* __restrict__ b1,
    const float* __restrict__ g1, const float* __restrict__ be1, int N, int E)
{
    extern __shared__ char smem[];
    const uint32_t sb = smem_u32(smem);
    __half* sCh = (__half*)(smem + E_C);
    float* sP = (float*)(smem + E_P);

    int tid = threadIdx.x, wid = tid >> 5, lane = tid & 31;
    int m0 = (wid >> 2) * 16, n0 = (wid & 3) * 32;

    for (int i = tid; i < 128 * 64; i += 512) {
        int n = i >> 6, k = i & 63;
        __half hb = __float2half_rn(W1[(size_t)(128 + k) * DN + n]);
        unsigned short h = *(unsigned short*)&hb;
        uint32_t a = sb + E_BH + n * 128 + (((uint32_t)(2 * k)) ^ (((uint32_t)(n & 7)) << 4));
        asm volatile("st.shared.b16 [%0], %1;" :: "r"(a), "h"(h));
    }
    for (int i = tid; i < DN; i += 512) { sP[i] = b1[i]; sP[DN + i] = g1[i]; sP[2 * DN + i] = be1[i]; }

    const int is64 = g_is64;
    const long long* ei64 = (const long long*)eidx;
    const int*       ei32 = (const int*)eidx;

    int ntiles = (E + 63) >> 6;
    float4 va[2];

    auto GATHER = [&](int tt, float4* dst) {
#pragma unroll
        for (int j = 0; j < 2; ++j) {
            int i = tid + j * 512;
            int r = i >> 4, q = i & 15;
            int e = (tt << 6) + r;
            dst[j] = (e < E) ? *(const float4*)&ea[(size_t)e * DE + q * 4]
                             : make_float4(0.f, 0.f, 0.f, 0.f);
        }
    };
    auto CONVERT = [&](const float4* src) {
#pragma unroll
        for (int j = 0; j < 2; ++j) {
            int i = tid + j * 512;
            int r = i >> 4, q = i & 15;
            uint32_t h01, h23;
            pack4h(src[j], h01, h23);
            uint32_t a = sb + E_A + r * 128 + (((uint32_t)(8 * q)) ^ (((uint32_t)(r & 7)) << 4));
            asm volatile("st.shared.v2.b32 [%0], {%1,%2};" :: "r"(a), "r"(h01), "r"(h23));
        }
    };

    int t = blockIdx.x;
    if (t < ntiles) { GATHER(t, va); CONVERT(va); }
    __syncthreads();

    for (; t < ntiles; t += gridDim.x) {
        int tn = t + gridDim.x;
        if (tn < ntiles) GATHER(tn, va);

        float c[4][4];
        mma_core1h<128, 4>(sb + E_A, sb + E_BH, m0, n0, lane, c);

        // store C as fp16, conflict-free stride
        int rlo = lane >> 2, cp = (lane & 3) * 2;
#pragma unroll
        for (int nt = 0; nt < 4; ++nt) {
            int row = m0 + rlo, col = n0 + nt * 8 + cp;
            *(__half2*)&sCh[row * ECSTRIDE + col]       = __floats2half2_rn(c[nt][0], c[nt][1]);
            *(__half2*)&sCh[(row + 8) * ECSTRIDE + col] = __floats2half2_rn(c[nt][2], c[nt][3]);
        }
        __syncthreads();   // C visible; all mma A-reads done

        // epilogue: warp owns rows [4*wid, 4*wid+4)
        {
            int e0 = t << 6;
            int c0 = lane * 4;
            float4 bb  = *(const float4*)&sP[c0];
            float4 gg  = *(const float4*)&sP[DN + c0];
            float4 beb = *(const float4*)&sP[2 * DN + c0];
#pragma unroll
            for (int j = 0; j < 4; ++j) {
                int r = wid * 4 + j;
                int e = e0 + r;
                int src = 0, dst = 0;
                if (e < E) {
                    src = is64 ? (int)ei64[e] : ei32[e];
                    dst = is64 ? (int)ei64[(size_t)E + e] : ei32[E + e];
                }
                float4 xp = (e < E) ? *(const float4*)&g_xp[(size_t)src * DN + c0]
                                    : make_float4(0.f, 0.f, 0.f, 0.f);
                uint2 u = *(const uint2*)&sCh[r * ECSTRIDE + c0];
                __half2 ch0 = *(__half2*)&u.x, ch1 = *(__half2*)&u.y;
                float v0 = __low2float(ch0)  + xp.x + bb.x;
                float v1 = __high2float(ch0) + xp.y + bb.y;
                float v2 = __low2float(ch1)  + xp.z + bb.z;
                float v3 = __high2float(ch1) + xp.w + bb.w;
                float s = v0 + v1 + v2 + v3;
                float q = fmaf(v0, v0, fmaf(v1, v1, fmaf(v2, v2, v3 * v3)));
#pragma unroll
                for (int o = 16; o > 0; o >>= 1) {
                    s += __shfl_xor_sync(0xffffffffu, s, o);
                    q += __shfl_xor_sync(0xffffffffu, q, o);
                }
                const float inv = 0.0078125f;
                float mean = s * inv;
                float var  = fmaf(q, inv, -mean * mean);
                float rstd = rsqrtf(var + 1e-5f);
                float o0 = lrelu(fmaf((v0 - mean) * rstd, gg.x, beb.x));
                float o1 = lrelu(fmaf((v1 - mean) * rstd, gg.y, beb.y));
                float o2 = lrelu(fmaf((v2 - mean) * rstd, gg.z, beb.z));
                float o3 = lrelu(fmaf((v3 - mean) * rstd, gg.w, beb.w));
                if (e < E) {
                    float* p = g_sums + (size_t)dst * DN + c0;
                    asm volatile("red.global.add.v4.f32 [%0], {%1,%2,%3,%4};"
                                 :: "l"(p), "f"(o0), "f"(o1), "f"(o2), "f"(o3) : "memory");
                    if (lane == 0) atomicAdd(g_cnt + dst, 1.0f);
                }
            }
        }

        if (tn < ntiles) CONVERT(va);
        __syncthreads();   // A(tn) ready; C reads done
    }
}

// ---------------- node kernel: 768 thr, 96-row tiles, fp16 2-term ---------------
#define N_BH 0
#define N_A  32768
#define N_AL 57344
#define N_C  81920
#define N_P  132608
#define SMEM_NODE 134144

__global__ void __launch_bounds__(768, 1) node_kernel(
    const float* __restrict__ x, const float* __restrict__ W2,
    const float* __restrict__ b2, const float* __restrict__ g2,
    const float* __restrict__ be2, float* __restrict__ out, int N)
{
    extern __shared__ char smem[];
    const uint32_t sb = smem_u32(smem);
    float* sC = (float*)(smem + N_C);
    float* sP = (float*)(smem + N_P);

    int tid = threadIdx.x, wid = tid >> 5, lane = tid & 31;
    int m0 = (wid >> 2) * 16, n0 = (wid & 3) * 32;

    for (int i = tid; i < 128 * 128; i += 768) {
        int n = i >> 7, k = i & 127;
        __half hb = __float2half_rn(W2[(size_t)k * DN + n]);
        unsigned short h = *(unsigned short*)&hb;
        uint32_t a = sb + N_BH + n * 256 + (((uint32_t)(2 * k)) ^ (((uint32_t)(n & 7)) << 4));
        asm volatile("st.shared.b16 [%0], %1;" :: "r"(a), "h"(h));
    }
    for (int i = tid; i < DN; i += 768) { sP[i] = b2[i]; sP[DN + i] = g2[i]; sP[2 * DN + i] = be2[i]; }

    int ntiles = (N + 95) / 96;
    float4 v[4];

    int t = blockIdx.x;
    if (t < ntiles) {
        int nb = t * 96;
#pragma unroll
        for (int j = 0; j < 4; ++j) {
            int i = tid + j * 768;
            int r = i >> 5, q = i & 31;
            int n = nb + r;
            float4 val = make_float4(0.f, 0.f, 0.f, 0.f);
            if (n < N) {
                float sc = 1.0f / fmaxf(g_cnt[n], 1.0f);
                val = *(const float4*)&g_sums[(size_t)n * DN + q * 4];
                val.x *= sc; val.y *= sc; val.z *= sc; val.w *= sc;
            }
            v[j] = val;
        }
#pragma unroll
        for (int j = 0; j < 4; ++j) {
            int i = tid + j * 768;
            int r = i >> 5, q = i & 31;
            uint32_t h01, h23, l01, l23;
            split4h(v[j], h01, h23, l01, l23);
            uint32_t a = sb + N_A + r * 256 + (((uint32_t)(8 * q)) ^ (((uint32_t)(r & 7)) << 4));
            asm volatile("st.shared.v2.b32 [%0], {%1,%2};" :: "r"(a), "r"(h01), "r"(h23));
            asm volatile("st.shared.v2.b32 [%0], {%1,%2};" :: "r"(a + (N_AL - N_A)), "r"(l01), "r"(l23));
        }
    }
    __syncthreads();

    for (; t < ntiles; t += gridDim.x) {
        int tn = t + gridDim.x;
        if (tn < ntiles) {
            int nb = tn * 96;
#pragma unroll
            for (int j = 0; j < 4; ++j) {
                int i = tid + j * 768;
                int r = i >> 5, q = i & 31;
                int n = nb + r;
                float4 val = make_float4(0.f, 0.f, 0.f, 0.f);
                if (n < N) {
                    float sc = 1.0f / fmaxf(g_cnt[n], 1.0f);
                    val = *(const float4*)&g_sums[(size_t)n * DN + q * 4];
                    val.x *= sc; val.y *= sc; val.z *= sc; val.w *= sc;
                }
                v[j] = val;
            }
        }

        float c[4][4];
        mma_core2h<256, 8>(sb + N_A, sb + N_AL, sb + N_BH, m0, n0, lane, c);

        int rlo = lane >> 2, cp = (lane & 3) * 2;
#pragma unroll
        for (int nt = 0; nt < 4; ++nt) {
            int row = m0 + rlo, col = n0 + nt * 8 + cp;
            *(float2*)&sC[row * CSTRIDE + col]       = make_float2(c[nt][0], c[nt][1]);
            *(float2*)&sC[(row + 8) * CSTRIDE + col] = make_float2(c[nt][2], c[nt][3]);
        }
        __syncthreads();

        {
            int nb = t * 96;
            int c0 = lane * 4;
            float4 bb  = *(const float4*)&sP[c0];
            float4 gg  = *(const float4*)&sP[DN + c0];
            float4 beb = *(const float4*)&sP[2 * DN + c0];
#pragma unroll
            for (int j = 0; j < 4; ++j) {
                int r = wid * 4 + j;
                int n = nb + r;
                float4 cv = *(const float4*)&sC[r * CSTRIDE + c0];
                float v0 = cv.x + bb.x, v1 = cv.y + bb.y, v2 = cv.z + bb.z, v3 = cv.w + bb.w;
                float s = v0 + v1 + v2 + v3;
                float q = fmaf(v0, v0, fmaf(v1, v1, fmaf(v2, v2, v3 * v3)));
#pragma unroll
                for (int o = 16; o > 0; o >>= 1) {
                    s += __shfl_xor_sync(0xffffffffu, s, o);
                    q += __shfl_xor_sync(0xffffffffu, q, o);
                }
                const float inv = 0.0078125f;
                float mean = s * inv;
                float var  = fmaf(q, inv, -mean * mean);
                float rstd = rsqrtf(var + 1e-5f);
                float o0 = lrelu(fmaf((v0 - mean) * rstd, gg.x, beb.x));
                float o1 = lrelu(fmaf((v1 - mean) * rstd, gg.y, beb.y));
                float o2 = lrelu(fmaf((v2 - mean) * rstd, gg.z, beb.z));
                float o3 = lrelu(fmaf((v3 - mean) * rstd, gg.w, beb.w));
                if (n < N) {
                    float4 xr = *(const float4*)&x[(size_t)n * DN + c0];
                    o0 = lrelu(o0 + xr.x);
                    o1 = lrelu(o1 + xr.y);
                    o2 = lrelu(o2 + xr.z);
                    o3 = lrelu(o3 + xr.w);
                    *(float4*)&out[(size_t)n * DN + c0] = make_float4(o0, o1, o2, o3);
                }
            }
        }

        if (tn < ntiles) {
#pragma unroll
            for (int j = 0; j < 4; ++j) {
                int i = tid + j * 768;
                int r = i >> 5, q = i & 31;
                uint32_t h01, h23, l01, l23;
                split4h(v[j], h01, h23, l01, l23);
                uint32_t a = sb + N_A + r * 256 + (((uint32_t)(8 * q)) ^ (((uint32_t)(r & 7)) << 4));
                asm volatile("st.shared.v2.b32 [%0], {%1,%2};" :: "r"(a), "r"(h01), "r"(h23));
                asm volatile("st.shared.v2.b32 [%0], {%1,%2};" :: "r"(a + (N_AL - N_A)), "r"(l01), "r"(l23));
            }
        }
        __syncthreads();
    }
}

// ---------------- launch ----------------------------------------------------------
extern "C" void kernel_launch(void* const* d_in, const int* in_sizes, int n_in,
                              void* d_out, int out_size)
{
    const float* x   = (const float*)d_in[0];
    const void*  ei  = d_in[1];
    const float* ea  = (const float*)d_in[2];
    const float* W1  = (const float*)d_in[3];
    const float* b1  = (const float*)d_in[4];
    const float* g1  = (const float*)d_in[5];
    const float* be1 = (const float*)d_in[6];
    const float* W2  = (const float*)d_in[7];
    const float* b2  = (const float*)d_in[8];
    const float* g2  = (const float*)d_in[9];
    const float* be2 = (const float*)d_in[10];
    float* out = (float*)d_out;

    int N = in_sizes[0] / DN;
    int E = in_sizes[2] / DE;

    cudaFuncSetAttribute(xprime_kernel, cudaFuncAttributeMaxDynamicSharedMemorySize, SMEM_XP);
    cudaFuncSetAttribute(edge_kernel,   cudaFuncAttributeMaxDynamicSharedMemorySize, SMEM_EDGE);
    cudaFuncSetAttribute(node_kernel,   cudaFuncAttributeMaxDynamicSharedMemorySize, SMEM_NODE);

    detect_kernel<<<1, 256>>>((const unsigned*)ei, E);
    zero_kernel<<<512, 256>>>(N);
    xprime_kernel<<<148, 768, SMEM_XP>>>(x, W1, N);
    edge_kernel<<<296, 512, SMEM_EDGE>>>(ei, ea, W1, b1, g1, be1, N, E);
    node_kernel<<<148, 768, SMEM_NODE>>>(x, W2, b2, g2, be2, out, N);
}